// round 3
// baseline (speedup 1.0000x reference)
#include <cuda_runtime.h>
#include <math.h>

#define TPB 96          // 3 warps: warp0=Y, warp1/2=chroma; 1 thread = one 8x8 block
#define BSTRIDE 65      // block stride in floats -> conflict-free gather/scatter

// Apply out = M * in * M^T (8x8, all in registers).
// Matches BOTH reference einsums: forward 'uvxy,...xy->...uv' and
// "inverse" 'xyuv,...uv->...xy' — the latter also contracts each axis
// with M (freq index first), not M^T.
__device__ __forceinline__ void mmt8(float* __restrict__ Bv, const float* __restrict__ M)
{
    // row pass: Bv <- Bv * M^T
    #pragma unroll
    for (int r = 0; r < 8; r++) {
        float t[8];
        #pragma unroll
        for (int u = 0; u < 8; u++) {
            float s = M[u * 8] * Bv[r * 8];
            #pragma unroll
            for (int x = 1; x < 8; x++) s = fmaf(M[u * 8 + x], Bv[r * 8 + x], s);
            t[u] = s;
        }
        #pragma unroll
        for (int u = 0; u < 8; u++) Bv[r * 8 + u] = t[u];
    }
    // col pass: Bv <- M * Bv
    #pragma unroll
    for (int c = 0; c < 8; c++) {
        float t[8];
        #pragma unroll
        for (int u = 0; u < 8; u++) {
            float s = M[u * 8] * Bv[c];
            #pragma unroll
            for (int x = 1; x < 8; x++) s = fmaf(M[u * 8 + x], Bv[x * 8 + c], s);
            t[u] = s;
        }
        #pragma unroll
        for (int u = 0; u < 8; u++) Bv[u * 8 + c] = t[u];
    }
}

__global__ __launch_bounds__(TPB, 3)
void jpeg_kernel(const float* __restrict__ img,
                 const float* __restrict__ r2y,
                 const float* __restrict__ y2r,
                 const float* __restrict__ C,
                 const float* __restrict__ ql,
                 const float* __restrict__ qc,
                 float* __restrict__ out,
                 int nbatch)
{
    __shared__ float sM[64];
    __shared__ float sQ[2][64];
    __shared__ float sQi[2][64];
    __shared__ float sB[TPB * BSTRIDE];

    const int tid = threadIdx.x;

    // ---- table init: recover 1-D DCT basis M from the 4-D coeff tensor ----
    if (tid < 64) {
        const float m00 = sqrtf(C[0]);                    // M[0][0]
        const int u = tid >> 3, x = tid & 7;
        sM[tid] = C[u * 512 + x * 8] / m00;               // C[u,0,x,0] = M[u,x]*M[0,0]
        const float a = ql[tid], b = qc[tid];
        sQ[0][tid] = a;  sQi[0][tid] = 1.0f / a;
        sQ[1][tid] = b;  sQi[1][tid] = 1.0f / b;
    }

    const int gx0 = blockIdx.x << 6;    // 64-wide region
    const int gy0 = blockIdx.y << 5;    // 32-tall region
    const size_t plane = 512 * 512;
    const float* src = img + (size_t)blockIdx.z * 3 * plane;
    float*       dst = out + (size_t)blockIdx.z * 3 * plane;

    const float A00 = r2y[0], A01 = r2y[1], A02 = r2y[2];
    const float A10 = r2y[3], A11 = r2y[4], A12 = r2y[5];
    const float A20 = r2y[6], A21 = r2y[7], A22 = r2y[8];

    // ---- phase 1: load RGB (float4), convert to scaled YUV, scatter block-major ----
    #pragma unroll
    for (int it = 0; it < 6; it++) {
        int v = tid + it * TPB;
        if (v < 512) {                       // 512 float4 groups in a 32x64 region
            int ly = v >> 4;                 // 0..31
            int lx = (v & 15) << 2;          // 0..60 step 4 (stays inside one 8-block)
            size_t poff = (size_t)(gy0 + ly) * 512 + (gx0 + lx);
            float4 R4 = *(const float4*)(src + poff);
            float4 G4 = *(const float4*)(src + plane + poff);
            float4 B4 = *(const float4*)(src + 2 * plane + poff);
            int blk  = ((ly >> 3) << 3) + (lx >> 3);          // 0..31 within channel
            int soff = ((ly & 7) << 3) + (lx & 7);
            float rr[4] = {R4.x, R4.y, R4.z, R4.w};
            float gg[4] = {G4.x, G4.y, G4.z, G4.w};
            float bb[4] = {B4.x, B4.y, B4.z, B4.w};
            #pragma unroll
            for (int j = 0; j < 4; j++) {
                float Y = fmaf(A02, bb[j], fmaf(A01, gg[j], A00 * rr[j]));
                float U = fmaf(A12, bb[j], fmaf(A11, gg[j], A10 * rr[j]));
                float V = fmaf(A22, bb[j], fmaf(A21, gg[j], A20 * rr[j]));
                sB[(blk     ) * BSTRIDE + soff + j] = Y * 255.0f - 128.0f;
                sB[(blk + 32) * BSTRIDE + soff + j] = U * 255.0f - 128.0f;
                sB[(blk + 64) * BSTRIDE + soff + j] = V * 255.0f - 128.0f;
            }
        }
    }

    __syncthreads();

    // ---- phase 2: per-thread 8x8: fwd M*B*M^T -> quant/dequant -> M*D*M^T, in registers ----
    {
        const int qi = (tid >= 32) ? 1 : 0;
        float M[64];
        #pragma unroll
        for (int j = 0; j < 64; j++) M[j] = sM[j];
        float Bv[64];
        float* myB = &sB[tid * BSTRIDE];
        #pragma unroll
        for (int j = 0; j < 64; j++) Bv[j] = myB[j];   // bank = (tid+j)%32 : conflict-free

        mmt8(Bv, M);                                   // forward DCT

        #pragma unroll
        for (int j = 0; j < 64; j++)
            Bv[j] = rintf(Bv[j] * sQi[qi][j]) * sQ[qi][j];   // round-half-even quant/dequant

        mmt8(Bv, M);                                   // reference "inverse" = same transform

        #pragma unroll
        for (int j = 0; j < 64; j++) myB[j] = Bv[j];
    }

    __syncthreads();

    // ---- phase 3: YUV' -> RGB, float4 stores ----
    const float D00 = y2r[0], D01 = y2r[1], D02 = y2r[2];
    const float D10 = y2r[3], D11 = y2r[4], D12 = y2r[5];
    const float D20 = y2r[6], D21 = y2r[7], D22 = y2r[8];
    const float inv255 = 1.0f / 255.0f;

    #pragma unroll
    for (int it = 0; it < 6; it++) {
        int v = tid + it * TPB;
        if (v < 512) {
            int ly = v >> 4;
            int lx = (v & 15) << 2;
            size_t poff = (size_t)(gy0 + ly) * 512 + (gx0 + lx);
            int blk  = ((ly >> 3) << 3) + (lx >> 3);
            int soff = ((ly & 7) << 3) + (lx & 7);
            float ro[4], go[4], bo[4];
            #pragma unroll
            for (int j = 0; j < 4; j++) {
                float Y = (sB[(blk     ) * BSTRIDE + soff + j] + 128.0f) * inv255;
                float U = (sB[(blk + 32) * BSTRIDE + soff + j] + 128.0f) * inv255;
                float V = (sB[(blk + 64) * BSTRIDE + soff + j] + 128.0f) * inv255;
                ro[j] = fmaf(D02, V, fmaf(D01, U, D00 * Y));
                go[j] = fmaf(D12, V, fmaf(D11, U, D10 * Y));
                bo[j] = fmaf(D22, V, fmaf(D21, U, D20 * Y));
            }
            *(float4*)(dst + poff)             = make_float4(ro[0], ro[1], ro[2], ro[3]);
            *(float4*)(dst + plane + poff)     = make_float4(go[0], go[1], go[2], go[3]);
            *(float4*)(dst + 2 * plane + poff) = make_float4(bo[0], bo[1], bo[2], bo[3]);
        }
    }
    (void)nbatch;
}

extern "C" void kernel_launch(void* const* d_in, const int* in_sizes, int n_in,
                              void* d_out, int out_size)
{
    const float* img = (const float*)d_in[0];
    const float* r2y = (const float*)d_in[1];
    const float* y2r = (const float*)d_in[2];
    const float* C   = (const float*)d_in[3];
    const float* ql  = (const float*)d_in[4];
    const float* qc  = (const float*)d_in[5];

    int nbatch = in_sizes[0] / (3 * 512 * 512);   // 16 for this problem
    dim3 grid(512 / 64, 512 / 32, nbatch);
    jpeg_kernel<<<grid, TPB>>>(img, r2y, y2r, C, ql, qc, (float*)d_out, nbatch);
}

// round 5
// speedup vs baseline: 1.3042x; 1.3042x over previous
#include <cuda_runtime.h>
#include <math.h>

#define TPB 96          // 3 warps: warp0=Y, warp1/2=chroma; 1 thread = one 8x8 block
#define BSTRIDE 65      // block stride in floats -> conflict-free gather/scatter

typedef unsigned long long u64;

// ---- packed f32x2 primitives (sm_103a; ptxas never auto-fuses these) ----
__device__ __forceinline__ u64 pk2(float lo, float hi) {
    u64 r; asm("mov.b64 %0,{%1,%2};" : "=l"(r) : "f"(lo), "f"(hi)); return r;
}
__device__ __forceinline__ void up2(u64 v, float& a, float& b) {
    asm("mov.b64 {%0,%1},%2;" : "=f"(a), "=f"(b) : "l"(v));
}
__device__ __forceinline__ u64 add2(u64 a, u64 b) {
    u64 d; asm("add.rn.f32x2 %0,%1,%2;" : "=l"(d) : "l"(a), "l"(b)); return d;
}
__device__ __forceinline__ u64 mul2(u64 a, u64 b) {
    u64 d; asm("mul.rn.f32x2 %0,%1,%2;" : "=l"(d) : "l"(a), "l"(b)); return d;
}
__device__ __forceinline__ u64 fma2(u64 a, u64 b, u64 c) {
    u64 d; asm("fma.rn.f32x2 %0,%1,%2,%3;" : "=l"(d) : "l"(a), "l"(b), "l"(c)); return d;
}

// One 8-point DCT pass over 4 packed lanes: A[k][j] <- sum_i M[k][i]*A[i][j],
// using even/odd symmetry M[u][x] = +/- M[u][7-x]. Me/Mo are duplicated-pair
// coefficient tables in shared memory (uniform LDS.64 broadcasts).
__device__ __forceinline__ void f8(u64 A[8][4], const u64* __restrict__ Me,
                                   const u64* __restrict__ Mo, u64 NEG1)
{
    #pragma unroll
    for (int j = 0; j < 4; j++) {
        u64 s0 = add2(A[0][j], A[7][j]);
        u64 s1 = add2(A[1][j], A[6][j]);
        u64 s2 = add2(A[2][j], A[5][j]);
        u64 s3 = add2(A[3][j], A[4][j]);
        u64 d0 = fma2(A[7][j], NEG1, A[0][j]);   // exact a-b
        u64 d1 = fma2(A[6][j], NEG1, A[1][j]);
        u64 d2 = fma2(A[5][j], NEG1, A[2][j]);
        u64 d3 = fma2(A[4][j], NEG1, A[3][j]);
        #pragma unroll
        for (int k = 0; k < 4; k++) {
            u64 e = mul2(Me[k * 4 + 0], s0);
            e = fma2(Me[k * 4 + 1], s1, e);
            e = fma2(Me[k * 4 + 2], s2, e);
            e = fma2(Me[k * 4 + 3], s3, e);
            u64 o = mul2(Mo[k * 4 + 0], d0);
            o = fma2(Mo[k * 4 + 1], d1, o);
            o = fma2(Mo[k * 4 + 2], d2, o);
            o = fma2(Mo[k * 4 + 3], d3, o);
            A[2 * k][j]     = e;
            A[2 * k + 1][j] = o;
        }
    }
}

// Pair-register 8x8 transpose: switches row-packed <-> column-packed form.
// Pure register traffic (mov.b64 splits/joins), no shared memory.
__device__ __forceinline__ void tr8(u64 A[8][4])
{
    float f[8][8];
    #pragma unroll
    for (int i = 0; i < 8; i++)
        #pragma unroll
        for (int j = 0; j < 4; j++) up2(A[i][j], f[i][2 * j], f[i][2 * j + 1]);
    #pragma unroll
    for (int j = 0; j < 4; j++)
        #pragma unroll
        for (int k = 0; k < 4; k++) {
            A[2 * j][k]     = pk2(f[2 * k][2 * j],     f[2 * k + 1][2 * j]);
            A[2 * j + 1][k] = pk2(f[2 * k][2 * j + 1], f[2 * k + 1][2 * j + 1]);
        }
}

__global__ __launch_bounds__(TPB, 3)
void jpeg_kernel(const float* __restrict__ img,
                 const float* __restrict__ r2y,
                 const float* __restrict__ y2r,
                 const float* __restrict__ C,
                 const float* __restrict__ ql,
                 const float* __restrict__ qc,
                 float* __restrict__ out,
                 int nbatch)
{
    __shared__ u64 sMe2[16];                 // duplicated-pair even coeffs M[2k][i], i=0..3
    __shared__ u64 sMo2[16];                 // duplicated-pair odd  coeffs M[2k+1][i]
    __shared__ __align__(16) float sQ[2][64];
    __shared__ __align__(16) float sQi[2][64];
    __shared__ float sB[TPB * BSTRIDE];

    const int tid = threadIdx.x;

    // ---- table init: recover 1-D DCT basis from the 4-D coeff tensor ----
    if (tid < 64) {
        const float a = ql[tid], b = qc[tid];
        sQ[0][tid] = a;  sQi[0][tid] = 1.0f / a;
        sQ[1][tid] = b;  sQi[1][tid] = 1.0f / b;
        if (tid < 16) {
            const float m00 = sqrtf(C[0]);               // M[0][0]
            const int k = tid >> 2, i = tid & 3;
            float me = C[(2 * k) * 512 + i * 8] / m00;   // C[u,0,x,0] = M[u,x]*M[0,0]
            float mo = C[(2 * k + 1) * 512 + i * 8] / m00;
            sMe2[tid] = pk2(me, me);
            sMo2[tid] = pk2(mo, mo);
        }
    }

    const int gx0 = blockIdx.x << 6;    // 64-wide region
    const int gy0 = blockIdx.y << 5;    // 32-tall region
    const size_t plane = 512 * 512;
    const float* src = img + (size_t)blockIdx.z * 3 * plane;
    float*       dst = out + (size_t)blockIdx.z * 3 * plane;

    const float A00 = r2y[0], A01 = r2y[1], A02 = r2y[2];
    const float A10 = r2y[3], A11 = r2y[4], A12 = r2y[5];
    const float A20 = r2y[6], A21 = r2y[7], A22 = r2y[8];

    // ---- phase 1: load RGB (float4), convert to scaled YUV, scatter block-major ----
    #pragma unroll
    for (int it = 0; it < 6; it++) {
        int v = tid + it * TPB;
        if (v < 512) {                       // 512 float4 groups in a 32x64 region
            int ly = v >> 4;                 // 0..31
            int lx = (v & 15) << 2;          // 0..60 step 4 (stays inside one 8-block)
            size_t poff = (size_t)(gy0 + ly) * 512 + (gx0 + lx);
            float4 R4 = *(const float4*)(src + poff);
            float4 G4 = *(const float4*)(src + plane + poff);
            float4 B4 = *(const float4*)(src + 2 * plane + poff);
            int blk  = ((ly >> 3) << 3) + (lx >> 3);          // 0..31 within channel
            int soff = ((ly & 7) << 3) + (lx & 7);
            float rr[4] = {R4.x, R4.y, R4.z, R4.w};
            float gg[4] = {G4.x, G4.y, G4.z, G4.w};
            float bb[4] = {B4.x, B4.y, B4.z, B4.w};
            #pragma unroll
            for (int j = 0; j < 4; j++) {
                float Y = fmaf(A02, bb[j], fmaf(A01, gg[j], A00 * rr[j]));
                float U = fmaf(A12, bb[j], fmaf(A11, gg[j], A10 * rr[j]));
                float V = fmaf(A22, bb[j], fmaf(A21, gg[j], A20 * rr[j]));
                sB[(blk     ) * BSTRIDE + soff + j] = Y * 255.0f - 128.0f;
                sB[(blk + 32) * BSTRIDE + soff + j] = U * 255.0f - 128.0f;
                sB[(blk + 64) * BSTRIDE + soff + j] = V * 255.0f - 128.0f;
            }
        }
    }

    __syncthreads();

    // ---- phase 2: per-thread 8x8 (packed f32x2, even/odd fast DCT) ----
    {
        const int qi = (tid >= 32) ? 1 : 0;
        const u64 NEG1 = pk2(-1.0f, -1.0f);
        float* myB = &sB[tid * BSTRIDE];

        u64 A[8][4];
        // load + pack pairs of rows: A[x][rp] = (b[2rp][x], b[2rp+1][x])
        #pragma unroll
        for (int rp = 0; rp < 4; rp++)
            #pragma unroll
            for (int x = 0; x < 8; x++)
                A[x][rp] = pk2(myB[(2 * rp) * 8 + x], myB[(2 * rp + 1) * 8 + x]);

        f8(A, sMe2, sMo2, NEG1);     // forward row pass (SIMD over rows)
        tr8(A);                      // row-packed -> column-packed
        f8(A, sMe2, sMo2, NEG1);     // forward col pass (SIMD over cols)

        // quantize / dequantize, column-packed; round-half-even matches jnp.round
        #pragma unroll
        for (int v = 0; v < 8; v++)
            #pragma unroll
            for (int up = 0; up < 4; up++) {
                float2 qi2 = *(const float2*)(&sQi[qi][v * 8 + 2 * up]);
                float2 q2  = *(const float2*)(&sQ[qi][v * 8 + 2 * up]);
                u64 t = mul2(A[v][up], pk2(qi2.x, qi2.y));
                float x0, x1; up2(t, x0, x1);
                A[v][up] = mul2(pk2(rintf(x0), rintf(x1)), pk2(q2.x, q2.y));
            }

        f8(A, sMe2, sMo2, NEG1);     // "inverse" col pass (reference reuses M)
        tr8(A);                      // column-packed -> row-packed
        f8(A, sMe2, sMo2, NEG1);     // "inverse" row pass

        // unpack + store
        #pragma unroll
        for (int wp = 0; wp < 4; wp++)
            #pragma unroll
            for (int y = 0; y < 8; y++) {
                float a, b; up2(A[y][wp], a, b);
                myB[(2 * wp) * 8 + y]     = a;
                myB[(2 * wp + 1) * 8 + y] = b;
            }
    }

    __syncthreads();

    // ---- phase 3: YUV' -> RGB, float4 stores ----
    const float D00 = y2r[0], D01 = y2r[1], D02 = y2r[2];
    const float D10 = y2r[3], D11 = y2r[4], D12 = y2r[5];
    const float D20 = y2r[6], D21 = y2r[7], D22 = y2r[8];
    const float inv255 = 1.0f / 255.0f;

    #pragma unroll
    for (int it = 0; it < 6; it++) {
        int v = tid + it * TPB;
        if (v < 512) {
            int ly = v >> 4;
            int lx = (v & 15) << 2;
            size_t poff = (size_t)(gy0 + ly) * 512 + (gx0 + lx);
            int blk  = ((ly >> 3) << 3) + (lx >> 3);
            int soff = ((ly & 7) << 3) + (lx & 7);
            float ro[4], go[4], bo[4];
            #pragma unroll
            for (int j = 0; j < 4; j++) {
                float Y = (sB[(blk     ) * BSTRIDE + soff + j] + 128.0f) * inv255;
                float U = (sB[(blk + 32) * BSTRIDE + soff + j] + 128.0f) * inv255;
                float V = (sB[(blk + 64) * BSTRIDE + soff + j] + 128.0f) * inv255;
                ro[j] = fmaf(D02, V, fmaf(D01, U, D00 * Y));
                go[j] = fmaf(D12, V, fmaf(D11, U, D10 * Y));
                bo[j] = fmaf(D22, V, fmaf(D21, U, D20 * Y));
            }
            *(float4*)(dst + poff)             = make_float4(ro[0], ro[1], ro[2], ro[3]);
            *(float4*)(dst + plane + poff)     = make_float4(go[0], go[1], go[2], go[3]);
            *(float4*)(dst + 2 * plane + poff) = make_float4(bo[0], bo[1], bo[2], bo[3]);
        }
    }
    (void)nbatch;
}

extern "C" void kernel_launch(void* const* d_in, const int* in_sizes, int n_in,
                              void* d_out, int out_size)
{
    const float* img = (const float*)d_in[0];
    const float* r2y = (const float*)d_in[1];
    const float* y2r = (const float*)d_in[2];
    const float* C   = (const float*)d_in[3];
    const float* ql  = (const float*)d_in[4];
    const float* qc  = (const float*)d_in[5];

    int nbatch = in_sizes[0] / (3 * 512 * 512);   // 16 for this problem
    dim3 grid(512 / 64, 512 / 32, nbatch);
    jpeg_kernel<<<grid, TPB>>>(img, r2y, y2r, C, ql, qc, (float*)d_out, nbatch);
}